// round 1
// baseline (speedup 1.0000x reference)
#include <cuda_runtime.h>
#include <cstdint>

#define NDIM 4096
#define NB   32
#define BSZ  128
#define LAT  64

// Scratch (static device globals; no allocation at runtime).
__device__ float g_G[(size_t)NB * NDIM * LAT];     // G[j][k][t] = sum_c L[k, j*128+c]*We[c][t], valid for k >= (j+1)*128
__device__ float g_Y[(size_t)NB * NDIM * LAT];     // Y[j][r][t] = (W[:,s:e]@We + W[:,e:]@G_j)[r][t]
__device__ float g_What[(size_t)NDIM * NDIM];      // quantized-reconstructed weight (pre row_norm)
__device__ unsigned char g_flags[NDIM * NB];       // nonzero flag per (row, block)

// ---------------------------------------------------------------------------
// A1: G[j][k][t] for k >= e_j. Block = 4 k-rows x 64 t. Grid (4096/4, 32).
// ---------------------------------------------------------------------------
__global__ void kernG(const float* __restrict__ L, const float* __restrict__ We) {
    int j  = blockIdx.y;
    int k0 = blockIdx.x * 4;
    int e  = (j + 1) * BSZ;
    if (k0 < e) return;                      // only rows k >= e_j are ever read

    __shared__ __align__(16) float Ls[4][BSZ];
    int tid = threadIdx.x;                   // 256 threads
    {
        int kk = tid >> 6;                   // 0..3
        int c0 = (tid & 63) * 2;             // 0..126
        const float* src = L + (size_t)(k0 + kk) * NDIM + j * BSZ + c0;
        Ls[kk][c0]     = src[0];
        Ls[kk][c0 + 1] = src[1];
    }
    __syncthreads();

    int kk = tid >> 6;       // 0..3
    int t  = tid & 63;       // 0..63
    float acc = 0.f;
#pragma unroll 8
    for (int c = 0; c < BSZ; ++c)
        acc = fmaf(Ls[kk][c], We[c * LAT + t], acc);
    g_G[((size_t)j * NDIM + k0 + kk) * LAT + t] = acc;
}

// ---------------------------------------------------------------------------
// A2: Y[j] = W[:, s_j:4096] @ M_j  where M_j rows are We (k in [s,e)) then G_j.
// Tile: 128(m) x 64(t), BK=16, 256 threads, each thread 4x8. Grid (32, 32).
// Pure fp32 FFMA (precision-critical: feeds round()).
// ---------------------------------------------------------------------------
#define A2_BK 16
__global__ void kernY(const float* __restrict__ W, const float* __restrict__ We) {
    __shared__ __align__(16) float As[A2_BK][128];
    __shared__ __align__(16) float Bs[A2_BK][64];

    int mt = blockIdx.x;             // 0..31
    int j  = blockIdx.y;             // 0..31
    int s  = j * BSZ;
    int e  = s + BSZ;
    int row0 = mt * 128;
    int tid  = threadIdx.x;          // 256

    int tr = tid >> 3;               // 0..31 : m-groups of 4
    int tc = tid & 7;                // 0..7  : t-groups of 8

    int a_r = tid >> 1;              // 0..127
    int a_k = (tid & 1) * 8;         // 0 or 8
    int b_k = tid >> 4;              // 0..15
    int b_t = (tid & 15) * 4;        // 0..60

    float acc[4][8];
#pragma unroll
    for (int i = 0; i < 4; ++i)
#pragma unroll
        for (int q = 0; q < 8; ++q) acc[i][q] = 0.f;

    for (int k0 = s; k0 < NDIM; k0 += A2_BK) {
        const float4* ap = reinterpret_cast<const float4*>(W + (size_t)(row0 + a_r) * NDIM + k0 + a_k);
        float4 av0 = ap[0];
        float4 av1 = ap[1];
        As[a_k + 0][a_r] = av0.x; As[a_k + 1][a_r] = av0.y;
        As[a_k + 2][a_r] = av0.z; As[a_k + 3][a_r] = av0.w;
        As[a_k + 4][a_r] = av1.x; As[a_k + 5][a_r] = av1.y;
        As[a_k + 6][a_r] = av1.z; As[a_k + 7][a_r] = av1.w;

        const float* bsrc = (k0 < e)
            ? (We + (size_t)(k0 + b_k - s) * LAT + b_t)
            : (g_G + ((size_t)j * NDIM + k0 + b_k) * LAT + b_t);
        float4 bv = *reinterpret_cast<const float4*>(bsrc);
        *reinterpret_cast<float4*>(&Bs[b_k][b_t]) = bv;

        __syncthreads();
#pragma unroll
        for (int kk = 0; kk < A2_BK; ++kk) {
            float4 a4  = *reinterpret_cast<const float4*>(&As[kk][tr * 4]);
            float4 b40 = *reinterpret_cast<const float4*>(&Bs[kk][tc * 8]);
            float4 b41 = *reinterpret_cast<const float4*>(&Bs[kk][tc * 8 + 4]);
            float a[4] = {a4.x, a4.y, a4.z, a4.w};
            float b[8] = {b40.x, b40.y, b40.z, b40.w, b41.x, b41.y, b41.z, b41.w};
#pragma unroll
            for (int i = 0; i < 4; ++i)
#pragma unroll
                for (int q = 0; q < 8; ++q)
                    acc[i][q] = fmaf(a[i], b[q], acc[i][q]);
        }
        __syncthreads();
    }

#pragma unroll
    for (int i = 0; i < 4; ++i)
#pragma unroll
        for (int q = 0; q < 8; ++q)
            g_Y[((size_t)j * NDIM + row0 + tr * 4 + i) * LAT + tc * 8 + q] = acc[i][q];
}

// ---------------------------------------------------------------------------
// B: one sequential quantization step for block jb.
// y = (Y[jb] - W_hat[:,e:] @ G_jb) / row_norm ; y_hat = rint(y);
// x_hat = y_hat @ Wd -> W_hat block + flag.  4 rows/block, 64 thr/row.
// ---------------------------------------------------------------------------
__global__ void kernStep(const float* __restrict__ rn, const float* __restrict__ Wd, int jb) {
    int rloc = threadIdx.x >> 6;           // 0..3
    int t    = threadIdx.x & 63;           // 0..63
    int r    = blockIdx.x * 4 + rloc;

    __shared__ float s_yh[4][64];
    __shared__ int   s_nz[4];
    if (threadIdx.x < 4) s_nz[threadIdx.x] = 0;
    __syncthreads();

    float y = g_Y[((size_t)jb * NDIM + r) * LAT + t];

    for (int jj = jb + 1; jj < NB; ++jj) {
        if (g_flags[r * NB + jj]) {
            const float* wh = g_What + (size_t)r * NDIM + jj * BSZ;
            const float* gp = g_G + ((size_t)jb * NDIM + jj * BSZ) * LAT + t;
#pragma unroll 4
            for (int k = 0; k < BSZ; ++k)
                y -= wh[k] * gp[k * LAT];
        }
    }

    y = y / rn[r];
    float yh = rintf(y);                   // round-half-even, matches jnp.round
    s_yh[rloc][t] = yh;
    if (yh != 0.f) s_nz[rloc] = 1;
    __syncthreads();

    float x0 = 0.f, x1 = 0.f;
    if (s_nz[rloc]) {
#pragma unroll 8
        for (int tt = 0; tt < 64; ++tt) {
            float v = s_yh[rloc][tt];
            x0 = fmaf(v, Wd[tt * BSZ + t], x0);
            x1 = fmaf(v, Wd[tt * BSZ + t + 64], x1);
        }
    }
    float* dst = g_What + (size_t)r * NDIM + jb * BSZ;
    dst[t]      = x0;
    dst[t + 64] = x1;
    if (t == 0) g_flags[r * NB + jb] = (unsigned char)s_nz[rloc];
}

// ---------------------------------------------------------------------------
// C: out[b,m] = bias[m] + sum_k x[b,k] * (W_hat[m,k]*rn[m]),
// skipping k-blocks whose 64-row m-tile flag OR is zero (bit-exact skip).
// Tile 64(b) x 64(m), BK=16, 256 threads, 4x4/thread. Grid (64, 64).
// ---------------------------------------------------------------------------
__global__ void kernOut(const float* __restrict__ x, const float* __restrict__ rn,
                        const float* __restrict__ bias, float* __restrict__ out) {
    __shared__ __align__(16) float xs[16][64];
    __shared__ __align__(16) float ws[16][64];
    __shared__ unsigned char shf[NB];

    int b0 = blockIdx.x * 64;
    int m0 = blockIdx.y * 64;
    int tid = threadIdx.x;

    if (tid < NB) {
        unsigned char f = 0;
        for (int mm = 0; mm < 64; ++mm) f |= g_flags[(m0 + mm) * NB + tid];
        shf[tid] = f;
    }
    __syncthreads();

    int tr = tid >> 4;         // 0..15 (b-groups of 4)
    int tc = tid & 15;         // 0..15 (m-groups of 4)
    int l_r = tid >> 2;        // 0..63
    int l_q = (tid & 3) * 4;   // 0,4,8,12

    float acc[4][4];
#pragma unroll
    for (int i = 0; i < 4; ++i)
#pragma unroll
        for (int q = 0; q < 4; ++q) acc[i][q] = 0.f;

    float rnm = rn[m0 + l_r];

    for (int jj = 0; jj < NB; ++jj) {
        if (!shf[jj]) continue;           // uniform across block
        for (int k0 = 0; k0 < BSZ; k0 += 16) {
            float4 xv = *reinterpret_cast<const float4*>(x + (size_t)(b0 + l_r) * NDIM + jj * BSZ + k0 + l_q);
            xs[l_q + 0][l_r] = xv.x; xs[l_q + 1][l_r] = xv.y;
            xs[l_q + 2][l_r] = xv.z; xs[l_q + 3][l_r] = xv.w;
            float4 wv = *reinterpret_cast<const float4*>(g_What + (size_t)(m0 + l_r) * NDIM + jj * BSZ + k0 + l_q);
            ws[l_q + 0][l_r] = wv.x * rnm; ws[l_q + 1][l_r] = wv.y * rnm;
            ws[l_q + 2][l_r] = wv.z * rnm; ws[l_q + 3][l_r] = wv.w * rnm;
            __syncthreads();
#pragma unroll
            for (int kk = 0; kk < 16; ++kk) {
                float4 a4 = *reinterpret_cast<const float4*>(&xs[kk][tr * 4]);
                float4 b4 = *reinterpret_cast<const float4*>(&ws[kk][tc * 4]);
                float a[4] = {a4.x, a4.y, a4.z, a4.w};
                float b[4] = {b4.x, b4.y, b4.z, b4.w};
#pragma unroll
                for (int i = 0; i < 4; ++i)
#pragma unroll
                    for (int q = 0; q < 4; ++q)
                        acc[i][q] = fmaf(a[i], b[q], acc[i][q]);
            }
            __syncthreads();
        }
    }

#pragma unroll
    for (int i = 0; i < 4; ++i) {
        int b = b0 + tr * 4 + i;
#pragma unroll
        for (int q = 0; q < 4; ++q) {
            int m = m0 + tc * 4 + q;
            out[(size_t)b * NDIM + m] = bias[m] + acc[i][q];
        }
    }
}

// ---------------------------------------------------------------------------
// kernel_launch: inputs (metadata order): x, weight, bias, row_norm, L, We, Wd
// ---------------------------------------------------------------------------
extern "C" void kernel_launch(void* const* d_in, const int* in_sizes, int n_in,
                              void* d_out, int out_size) {
    const float* x      = (const float*)d_in[0];
    const float* weight = (const float*)d_in[1];
    const float* bias   = (const float*)d_in[2];
    const float* rn     = (const float*)d_in[3];
    const float* L      = (const float*)d_in[4];
    const float* We     = (const float*)d_in[5];
    const float* Wd     = (const float*)d_in[6];
    float* out          = (float*)d_out;

    // A1: G_j = Lmask_j @ We  (parallel over j)
    kernG<<<dim3(NDIM / 4, NB), 256>>>(L, We);
    // A2: Y_j = W[:, s_j:] @ [We ; G_j]  (the heavy fp32 GEMM, loop-independent)
    kernY<<<dim3(NDIM / 128, NB), 256>>>(weight, We);
    // B: 32 sequential quantization steps (block 31 down to 0)
    for (int jb = NB - 1; jb >= 0; --jb)
        kernStep<<<NDIM / 4, 256>>>(rn, Wd, jb);
    // C: out = bias + x @ (W_hat * rn)^T with exact zero-block skipping
    kernOut<<<dim3(NDIM / 64, NDIM / 64), 256>>>(x, rn, bias, out);
}

// round 4
// speedup vs baseline: 2.0327x; 2.0327x over previous
#include <cuda_runtime.h>
#include <cuda_bf16.h>
#include <cstdint>

#define NDIM 4096
#define NB   32
#define BSZ  128
#define LAT  64
#define NCOL (NB * LAT)   // 2048

// Static device scratch; [0] = hi, [1] = lo  (value = hi + lo, bf16x2 split).
__device__ __nv_bfloat16 g_Wb[2][(size_t)NDIM * NDIM];
__device__ __nv_bfloat16 g_Lb[2][(size_t)NDIM * NDIM];
__device__ __nv_bfloat16 g_Mt[2][(size_t)NCOL * NDIM];   // Mt[n,k] = M[k,n]
__device__ __nv_bfloat16 g_WeT[2][LAT * BSZ];            // WeT[t,c] = We[c,t]
__device__ float g_Y[(size_t)NDIM * NCOL];
__device__ float g_What[(size_t)NDIM * NDIM];            // zero-init; written only where flag set
__device__ unsigned char g_flags[NDIM * NB];

// ---------------------------------------------------------------------------
// Base-target helpers (sm_80+): cp.async, ldmatrix, mma.sync bf16
// ---------------------------------------------------------------------------
__device__ __forceinline__ uint32_t smem_u32(const void* p) {
    uint32_t a;
    asm("{ .reg .u64 t; cvta.to.shared.u64 t, %1; cvt.u32.u64 %0, t; }" : "=r"(a) : "l"(p));
    return a;
}
#define CP_ASYNC16(s, g) asm volatile("cp.async.cg.shared.global [%0], [%1], 16;" :: "r"(s), "l"(g))
#define CP_COMMIT()      asm volatile("cp.async.commit_group;" ::: "memory")
#define CP_WAIT(n)       asm volatile("cp.async.wait_group %0;" :: "n"(n) : "memory")

__device__ __forceinline__ void ldm_x4(uint32_t addr, uint32_t r[4]) {
    asm volatile("ldmatrix.sync.aligned.m8n8.x4.shared.b16 {%0,%1,%2,%3}, [%4];"
                 : "=r"(r[0]), "=r"(r[1]), "=r"(r[2]), "=r"(r[3]) : "r"(addr));
}
__device__ __forceinline__ void mma_bf16(float* c, const uint32_t a[4], uint32_t b0, uint32_t b1) {
    asm volatile(
        "mma.sync.aligned.m16n8k16.row.col.f32.bf16.bf16.f32 "
        "{%0,%1,%2,%3}, {%4,%5,%6,%7}, {%8,%9}, {%0,%1,%2,%3};"
        : "+f"(c[0]), "+f"(c[1]), "+f"(c[2]), "+f"(c[3])
        : "r"(a[0]), "r"(a[1]), "r"(a[2]), "r"(a[3]), "r"(b0), "r"(b1));
}
__device__ __forceinline__ void split2(float v, __nv_bfloat16& hi, __nv_bfloat16& lo) {
    hi = __float2bfloat16(v);
    lo = __float2bfloat16(v - __bfloat162float(hi));
}

#define RS 80   // smem row stride: 32 bf16 (64B) + 16B pad -> conflict-free ldmatrix

// ---------------------------------------------------------------------------
// Prep: fp32 -> (hi, lo) bf16 split
// ---------------------------------------------------------------------------
__global__ void kernCvt(const float* __restrict__ src, int which) {
    __nv_bfloat16* hi = which ? g_Lb[0] : g_Wb[0];
    __nv_bfloat16* lo = which ? g_Lb[1] : g_Wb[1];
    size_t idx = (size_t)blockIdx.x * blockDim.x + threadIdx.x;   // per 8 elems
    const float4* s = reinterpret_cast<const float4*>(src) + idx * 2;
    float4 a = s[0], b = s[1];
    float v[8] = {a.x, a.y, a.z, a.w, b.x, b.y, b.z, b.w};
    __nv_bfloat16 h[8], l[8];
#pragma unroll
    for (int q = 0; q < 8; ++q) split2(v[q], h[q], l[q]);
    *reinterpret_cast<uint4*>(hi + idx * 8) = *reinterpret_cast<uint4*>(h);
    *reinterpret_cast<uint4*>(lo + idx * 8) = *reinterpret_cast<uint4*>(l);
}

__global__ void kernWeT(const float* __restrict__ We) {
    int idx = blockIdx.x * blockDim.x + threadIdx.x;   // 8192
    int t = idx >> 7, c = idx & 127;
    __nv_bfloat16 h, l;
    split2(We[c * LAT + t], h, l);
    g_WeT[0][idx] = h;
    g_WeT[1][idx] = l;
}

__global__ void kernFillMt(const float* __restrict__ We) {
    int idx = blockIdx.x * blockDim.x + threadIdx.x;   // NCOL*512
    int n = idx >> 9, g = idx & 511, k0 = g * 8;
    int j = n >> 6, t = n & 63, s = j * BSZ;
    __nv_bfloat16 h[8], l[8];
    if (k0 >= s && k0 < s + BSZ) {
#pragma unroll
        for (int q = 0; q < 8; ++q) split2(We[(k0 + q - s) * LAT + t], h[q], l[q]);
    } else {
#pragma unroll
        for (int q = 0; q < 8; ++q) { h[q] = __float2bfloat16(0.f); l[q] = h[q]; }
    }
    *reinterpret_cast<uint4*>(g_Mt[0] + (size_t)n * NDIM + k0) = *reinterpret_cast<uint4*>(h);
    *reinterpret_cast<uint4*>(g_Mt[1] + (size_t)n * NDIM + k0) = *reinterpret_cast<uint4*>(l);
}

// ---------------------------------------------------------------------------
// kernG: Mt G-blocks.  C[t(64), kr(128)] = sum_c WeT[t,c] * L[k0+kr, s+c].
// Split-precision HMMA. Grid (32 kt, 32 j), active iff kt > j. 128 threads.
// Single-stage smem: A(hi,lo) 2x5120, B(hi,lo) 2x10240 = 30720 B.
// ---------------------------------------------------------------------------
__global__ void __launch_bounds__(128, 4) kernG() {
    int kt = blockIdx.x, j = blockIdx.y;
    if (kt <= j) return;
    extern __shared__ __align__(128) char sm[];
    uint32_t sb = smem_u32(sm);
    uint32_t sA[2] = {sb, sb + 5120};
    uint32_t sB[2] = {sb + 10240, sb + 20480};
    int tid = threadIdx.x, wid = tid >> 5, lane = tid & 31;
    int k0g = kt * BSZ, s = j * BSZ;
    int wm = (wid & 1) * 32, wn = (wid >> 1) * 64;

    float acc[2][8][4];
#pragma unroll
    for (int i = 0; i < 2; ++i)
#pragma unroll
        for (int q = 0; q < 8; ++q)
#pragma unroll
            for (int z = 0; z < 4; ++z) acc[i][q][z] = 0.f;

    for (int it = 0; it < 4; ++it) {            // K=128, BK=32
        int kk = it * 32;
#pragma unroll
        for (int q = 0; q < 4; ++q) {           // A: 64 rows x 4ch x 2prec = 512
            int id = tid + q * 128;
            int prec = id >> 8, rem = id & 255, row = rem >> 2, ch = rem & 3;
            CP_ASYNC16(sA[prec] + row * RS + ch * 16,
                       g_WeT[prec] + row * BSZ + kk + ch * 8);
        }
#pragma unroll
        for (int q = 0; q < 8; ++q) {           // B: 128 rows x 4ch x 2prec = 1024
            int id = tid + q * 128;
            int prec = id >> 9, rem = id & 511, row = rem >> 2, ch = rem & 3;
            CP_ASYNC16(sB[prec] + row * RS + ch * 16,
                       g_Lb[prec] + (size_t)(k0g + row) * NDIM + s + kk + ch * 8);
        }
        CP_COMMIT();
        CP_WAIT(0);
        __syncthreads();

#pragma unroll
        for (int ks = 0; ks < 2; ++ks) {
            uint32_t ah[2][4], al[2][4];
#pragma unroll
            for (int mf = 0; mf < 2; ++mf) {
                uint32_t ao = (wm + mf * 16 + (lane & 15)) * RS + ks * 32 + (lane >> 4) * 16;
                ldm_x4(sA[0] + ao, ah[mf]);
                ldm_x4(sA[1] + ao, al[mf]);
            }
            uint32_t bh[8][2];
#pragma unroll
            for (int p = 0; p < 4; ++p) {
                uint32_t r[4];
                int g = lane >> 3;
                int row = wn + p * 16 + ((g >> 1) << 3) + (lane & 7);
                ldm_x4(sB[0] + row * RS + ks * 32 + (g & 1) * 16, r);
                bh[p * 2][0] = r[0]; bh[p * 2][1] = r[1];
                bh[p * 2 + 1][0] = r[2]; bh[p * 2 + 1][1] = r[3];
            }
#pragma unroll
            for (int mf = 0; mf < 2; ++mf)
#pragma unroll
                for (int nf = 0; nf < 8; ++nf) {
                    mma_bf16(acc[mf][nf], ah[mf], bh[nf][0], bh[nf][1]);
                    mma_bf16(acc[mf][nf], al[mf], bh[nf][0], bh[nf][1]);
                }
            uint32_t bl[8][2];
#pragma unroll
            for (int p = 0; p < 4; ++p) {
                uint32_t r[4];
                int g = lane >> 3;
                int row = wn + p * 16 + ((g >> 1) << 3) + (lane & 7);
                ldm_x4(sB[1] + row * RS + ks * 32 + (g & 1) * 16, r);
                bl[p * 2][0] = r[0]; bl[p * 2][1] = r[1];
                bl[p * 2 + 1][0] = r[2]; bl[p * 2 + 1][1] = r[3];
            }
#pragma unroll
            for (int mf = 0; mf < 2; ++mf)
#pragma unroll
                for (int nf = 0; nf < 8; ++nf)
                    mma_bf16(acc[mf][nf], ah[mf], bl[nf][0], bl[nf][1]);
        }
        __syncthreads();
    }

    // store split(acc) -> Mt[(j*64+t), k0g+kr]
    int jn = j * LAT;
#pragma unroll
    for (int mf = 0; mf < 2; ++mf) {
        int t0 = wm + mf * 16 + (lane >> 2);
#pragma unroll
        for (int nf = 0; nf < 8; ++nf) {
            int kr = wn + nf * 8 + 2 * (lane & 3);
            __nv_bfloat16 h0, l0, h1, l1, h2, l2, h3, l3;
            split2(acc[mf][nf][0], h0, l0);
            split2(acc[mf][nf][1], h1, l1);
            split2(acc[mf][nf][2], h2, l2);
            split2(acc[mf][nf][3], h3, l3);
            size_t o0 = (size_t)(jn + t0) * NDIM + k0g + kr;
            size_t o1 = (size_t)(jn + t0 + 8) * NDIM + k0g + kr;
            *reinterpret_cast<__nv_bfloat162*>(g_Mt[0] + o0) = __nv_bfloat162(h0, h1);
            *reinterpret_cast<__nv_bfloat162*>(g_Mt[1] + o0) = __nv_bfloat162(l0, l1);
            *reinterpret_cast<__nv_bfloat162*>(g_Mt[0] + o1) = __nv_bfloat162(h2, h3);
            *reinterpret_cast<__nv_bfloat162*>(g_Mt[1] + o1) = __nv_bfloat162(l2, l3);
        }
    }
}

// ---------------------------------------------------------------------------
// kernGemmY: Y[4096,2048] = W @ M^T, split-precision HMMA (hi*hi+hi*lo+lo*hi).
// BM=128 BN=128 BK=32, 256 thr (8 warps 2x4, warp 64x32). Single-stage smem
// 40960 B; overlap via 2 CTAs/SM. k starts at n0*2 (triangular M).
// ---------------------------------------------------------------------------
__global__ void __launch_bounds__(256, 2) kernGemmY() {
    extern __shared__ __align__(128) char sm[];
    const int TSZ = 128 * RS;                 // 10240
    uint32_t sb = smem_u32(sm);
    uint32_t sA[2] = {sb, sb + TSZ};
    uint32_t sB[2] = {sb + 2 * TSZ, sb + 3 * TSZ};
    int tid = threadIdx.x, wid = tid >> 5, lane = tid & 31;
    int m0 = blockIdx.x * 128, n0 = blockIdx.y * 128;
    int kst = n0 * 2;
    int niter = (NDIM - kst) / 32;
    int wm = (wid & 1) * 64, wn = (wid >> 1) * 32;

    float acc[4][4][4];
#pragma unroll
    for (int i = 0; i < 4; ++i)
#pragma unroll
        for (int q = 0; q < 4; ++q)
#pragma unroll
            for (int z = 0; z < 4; ++z) acc[i][q][z] = 0.f;

    for (int it = 0; it < niter; ++it) {
        int k0 = kst + it * 32;
#pragma unroll
        for (int q = 0; q < 4; ++q) {          // 128 rows x 4ch x 2prec = 1024 each
            int id = tid + q * 256;
            int prec = id >> 9, rem = id & 511, row = rem >> 2, ch = rem & 3;
            CP_ASYNC16(sA[prec] + row * RS + ch * 16,
                       g_Wb[prec] + (size_t)(m0 + row) * NDIM + k0 + ch * 8);
            CP_ASYNC16(sB[prec] + row * RS + ch * 16,
                       g_Mt[prec] + (size_t)(n0 + row) * NDIM + k0 + ch * 8);
        }
        CP_COMMIT();
        CP_WAIT(0);
        __syncthreads();

#pragma unroll
        for (int ks = 0; ks < 2; ++ks) {
            uint32_t ah[4][4], al[4][4];
#pragma unroll
            for (int mf = 0; mf < 4; ++mf) {
                uint32_t ao = (wm + mf * 16 + (lane & 15)) * RS + ks * 32 + (lane >> 4) * 16;
                ldm_x4(sA[0] + ao, ah[mf]);
                ldm_x4(sA[1] + ao, al[mf]);
            }
            uint32_t bh[4][2];
#pragma unroll
            for (int p = 0; p < 2; ++p) {
                uint32_t r[4];
                int g = lane >> 3;
                int row = wn + p * 16 + ((g >> 1) << 3) + (lane & 7);
                ldm_x4(sB[0] + row * RS + ks * 32 + (g & 1) * 16, r);
                bh[p * 2][0] = r[0]; bh[p * 2][1] = r[1];
                bh[p * 2 + 1][0] = r[2]; bh[p * 2 + 1][1] = r[3];
            }
#pragma unroll
            for (int mf = 0; mf < 4; ++mf)
#pragma unroll
                for (int nf = 0; nf < 4; ++nf) {
                    mma_bf16(acc[mf][nf], ah[mf], bh[nf][0], bh[nf][1]);
                    mma_bf16(acc[mf][nf], al[mf], bh[nf][0], bh[nf][1]);
                }
            uint32_t bl[4][2];
#pragma unroll
            for (int p = 0; p < 2; ++p) {
                uint32_t r[4];
                int g = lane >> 3;
                int row = wn + p * 16 + ((g >> 1) << 3) + (lane & 7);
                ldm_x4(sB[1] + row * RS + ks * 32 + (g & 1) * 16, r);
                bl[p * 2][0] = r[0]; bl[p * 2][1] = r[1];
                bl[p * 2 + 1][0] = r[2]; bl[p * 2 + 1][1] = r[3];
            }
#pragma unroll
            for (int mf = 0; mf < 4; ++mf)
#pragma unroll
                for (int nf = 0; nf < 4; ++nf)
                    mma_bf16(acc[mf][nf], ah[mf], bl[nf][0], bl[nf][1]);
        }
        __syncthreads();
    }

#pragma unroll
    for (int mf = 0; mf < 4; ++mf) {
        int row = m0 + wm + mf * 16 + (lane >> 2);
#pragma unroll
        for (int nf = 0; nf < 4; ++nf) {
            int col = n0 + wn + nf * 8 + 2 * (lane & 3);
            *reinterpret_cast<float2*>(g_Y + (size_t)row * NCOL + col) =
                make_float2(acc[mf][nf][0], acc[mf][nf][1]);
            *reinterpret_cast<float2*>(g_Y + (size_t)(row + 8) * NCOL + col) =
                make_float2(acc[mf][nf][2], acc[mf][nf][3]);
        }
    }
}

// ---------------------------------------------------------------------------
// kernSteps: all 32 sequential quantization steps fused (row-local dependency).
// ---------------------------------------------------------------------------
__global__ void kernSteps(const float* __restrict__ rn, const float* __restrict__ Wd) {
    int rloc = threadIdx.x >> 6, t = threadIdx.x & 63;
    int r = blockIdx.x * 4 + rloc;

    __shared__ float s_yh[4][64];
    __shared__ int s_nz[4];
    __shared__ unsigned char fl[4][32];

    float rnv = rn[r];
    if (t < 32) fl[rloc][t] = 0;

    for (int jb = NB - 1; jb >= 0; --jb) {
        __syncthreads();
        if (t == 0) s_nz[rloc] = 0;
        __syncthreads();

        float y = g_Y[(size_t)r * NCOL + jb * LAT + t];
        for (int jj = jb + 1; jj < NB; ++jj) {
            if (fl[rloc][jj]) {
                const float* wh = g_What + (size_t)r * NDIM + jj * BSZ;
                size_t go = (size_t)(jb * LAT + t) * NDIM + jj * BSZ;
#pragma unroll 4
                for (int k = 0; k < BSZ; ++k) {
                    float gv = __bfloat162float(g_Mt[0][go + k]) +
                               __bfloat162float(g_Mt[1][go + k]);
                    y -= wh[k] * gv;
                }
            }
        }
        y /= rnv;
        float yh = rintf(y);
        s_yh[rloc][t] = yh;
        if (yh != 0.f) s_nz[rloc] = 1;
        __syncthreads();

        int nz = s_nz[rloc];
        if (nz) {
            float x0 = 0.f, x1 = 0.f;
#pragma unroll 8
            for (int tt = 0; tt < 64; ++tt) {
                float v = s_yh[rloc][tt];
                x0 = fmaf(v, Wd[tt * BSZ + t], x0);
                x1 = fmaf(v, Wd[tt * BSZ + t + 64], x1);
            }
            float* dst = g_What + (size_t)r * NDIM + jb * BSZ;
            dst[t] = x0;
            dst[t + 64] = x1;
        }
        if (t == 0) {
            fl[rloc][jb] = (unsigned char)nz;
            g_flags[r * NB + jb] = (unsigned char)nz;
        }
    }
}

// ---------------------------------------------------------------------------
// kernOut: out = bias + x @ (W_hat * rn)^T, skipping exactly-zero k-blocks.
// (Unwritten W_hat rows are zero: __device__ globals are zero-initialized.)
// ---------------------------------------------------------------------------
__global__ void kernOut(const float* __restrict__ x, const float* __restrict__ rn,
                        const float* __restrict__ bias, float* __restrict__ out) {
    __shared__ __align__(16) float xs[16][64];
    __shared__ __align__(16) float ws[16][64];
    __shared__ unsigned char shf[NB];

    int b0 = blockIdx.x * 64;
    int m0 = blockIdx.y * 64;
    int tid = threadIdx.x;

    if (tid < NB) {
        unsigned char f = 0;
        for (int mm = 0; mm < 64; ++mm) f |= g_flags[(m0 + mm) * NB + tid];
        shf[tid] = f;
    }
    __syncthreads();

    int tr = tid >> 4, tc = tid & 15;
    int l_r = tid >> 2, l_q = (tid & 3) * 4;

    float acc[4][4];
#pragma unroll
    for (int i = 0; i < 4; ++i)
#pragma unroll
        for (int q = 0; q < 4; ++q) acc[i][q] = 0.f;

    float rnm = rn[m0 + l_r];

    for (int jj = 0; jj < NB; ++jj) {
        if (!shf[jj]) continue;
        for (int k0 = 0; k0 < BSZ; k0 += 16) {
            float4 xv = *reinterpret_cast<const float4*>(x + (size_t)(b0 + l_r) * NDIM + jj * BSZ + k0 + l_q);
            xs[l_q + 0][l_r] = xv.x; xs[l_q + 1][l_r] = xv.y;
            xs[l_q + 2][l_r] = xv.z; xs[l_q + 3][l_r] = xv.w;
            float4 wv = *reinterpret_cast<const float4*>(g_What + (size_t)(m0 + l_r) * NDIM + jj * BSZ + k0 + l_q);
            ws[l_q + 0][l_r] = wv.x * rnm; ws[l_q + 1][l_r] = wv.y * rnm;
            ws[l_q + 2][l_r] = wv.z * rnm; ws[l_q + 3][l_r] = wv.w * rnm;
            __syncthreads();
#pragma unroll
            for (int kk = 0; kk < 16; ++kk) {
                float4 a4 = *reinterpret_cast<const float4*>(&xs[kk][tr * 4]);
                float4 b4 = *reinterpret_cast<const float4*>(&ws[kk][tc * 4]);
                float a[4] = {a4.x, a4.y, a4.z, a4.w};
                float b[4] = {b4.x, b4.y, b4.z, b4.w};
#pragma unroll
                for (int i = 0; i < 4; ++i)
#pragma unroll
                    for (int q = 0; q < 4; ++q)
                        acc[i][q] = fmaf(a[i], b[q], acc[i][q]);
            }
            __syncthreads();
        }
    }

#pragma unroll
    for (int i = 0; i < 4; ++i) {
        int b = b0 + tr * 4 + i;
#pragma unroll
        for (int q = 0; q < 4; ++q) {
            int m = m0 + tc * 4 + q;
            out[(size_t)b * NDIM + m] = bias[m] + acc[i][q];
        }
    }
}

// ---------------------------------------------------------------------------
// kernel_launch: inputs (metadata order): x, weight, bias, row_norm, L, We, Wd
// ---------------------------------------------------------------------------
extern "C" void kernel_launch(void* const* d_in, const int* in_sizes, int n_in,
                              void* d_out, int out_size) {
    (void)in_sizes; (void)n_in; (void)out_size;
    const float* x      = (const float*)d_in[0];
    const float* weight = (const float*)d_in[1];
    const float* bias   = (const float*)d_in[2];
    const float* rn     = (const float*)d_in[3];
    const float* L      = (const float*)d_in[4];
    const float* We     = (const float*)d_in[5];
    const float* Wd     = (const float*)d_in[6];
    float* out          = (float*)d_out;

    kernCvt<<<8192, 256>>>(weight, 0);                    // W -> (hi,lo) bf16
    kernCvt<<<8192, 256>>>(L, 1);                         // L -> (hi,lo) bf16
    kernWeT<<<32, 256>>>(We);                             // We^T split
    kernFillMt<<<4096, 256>>>(We);                        // Mt diag blocks split + zeros
    kernG<<<dim3(32, 32), 128, 30720>>>();                // Mt G-blocks, split HMMA
    kernGemmY<<<dim3(32, 16), 256, 40960>>>();            // Y = W @ M, split HMMA
    kernSteps<<<1024, 256>>>(rn, Wd);                     // 32 fused sequential steps
    kernOut<<<dim3(64, 64), 256>>>(x, rn, bias, out);     // output GEMM, zero-block skip
}